// round 2
// baseline (speedup 1.0000x reference)
#include <cuda_runtime.h>
#include <math.h>

// Problem constants (fixed shapes)
#define B      2
#define HEADS  8
#define CQ     48
#define CK     12
#define CTOT   384      // HEADS*CQ
#define P      96       // pooled channels = HEADS*CK
#define L      4096
#define TREP   16
#define HW     65536    // 256*256 = TREP*L
#define NROWS  (B*CTOT)     // 768 q rows
#define KROWS  (B*P)        // 192 k rows

// Scratch (static device globals — no allocation)
__device__ float g_kn[KROWS * L];      // pooled + L2-normalized kv
__device__ float g_attn[NROWS * CK];   // softmax(attn)
__device__ float g_M[B * CTOT * P];    // W folded with attn

__device__ __forceinline__ float warpSum(float v) {
#pragma unroll
    for (int o = 16; o > 0; o >>= 1) v += __shfl_xor_sync(0xffffffffu, v, o);
    return v;
}

// ---------------------------------------------------------------------------
// K2: avg_pool1d over channel groups of 4 + L2 normalize each pooled row.
// One block per pooled row (192 blocks). MUST run before k_fold_attn.
// ---------------------------------------------------------------------------
__global__ void __launch_bounds__(1024) k_pool_kv(const float* __restrict__ kv) {
    int row = blockIdx.x;               // b*P + i
    int b = row / P, i = row % P;
    int tid = threadIdx.x;
    const float4* base = reinterpret_cast<const float4*>(kv + ((size_t)b * CTOT + 4 * i) * L);
    float4 v0 = base[tid];
    float4 v1 = base[1024 + tid];
    float4 v2 = base[2048 + tid];
    float4 v3 = base[3072 + tid];
    float4 p;
    p.x = 0.25f * (v0.x + v1.x + v2.x + v3.x);
    p.y = 0.25f * (v0.y + v1.y + v2.y + v3.y);
    p.z = 0.25f * (v0.z + v1.z + v2.z + v3.z);
    p.w = 0.25f * (v0.w + v1.w + v2.w + v3.w);
    float ss = p.x * p.x + p.y * p.y + p.z * p.z + p.w * p.w;

    ss = warpSum(ss);
    __shared__ float sred[32];
    __shared__ float s_scale;
    int lane = tid & 31, w = tid >> 5;
    if (lane == 0) sred[w] = ss;
    __syncthreads();
    if (w == 0) {
        float v = sred[lane];
        v = warpSum(v);
        if (lane == 0) s_scale = 1.f / fmaxf(sqrtf(v), 1e-12f);
    }
    __syncthreads();
    float sc = s_scale;
    p.x *= sc; p.y *= sc; p.z *= sc; p.w *= sc;
    reinterpret_cast<float4*>(g_kn + (size_t)row * L)[tid] = p;
}

// ---------------------------------------------------------------------------
// K1' (fused): fold Q over 16 tiles, dot against the 12 kn rows on the fly,
// reduce, softmax, write attn row. One block per q-row (768 blocks).
// Reads 201MB of Q (dominant HBM read); kn reads stay in L2 (3MB resident).
// ---------------------------------------------------------------------------
__global__ void __launch_bounds__(1024) k_fold_attn(const float* __restrict__ Q) {
    int row = blockIdx.x;
    int b = row / CTOT;
    int c = row % CTOT;
    int h = c / CQ;
    int tid = threadIdx.x;
    int lane = tid & 31, w = tid >> 5;

    const float4* qp = reinterpret_cast<const float4*>(Q + (size_t)row * HW);
    float4 acc = make_float4(0.f, 0.f, 0.f, 0.f);
    float ss = 0.f;
#pragma unroll
    for (int t = 0; t < TREP; t++) {
        float4 v = qp[t * 1024 + tid];
        acc.x += v.x; acc.y += v.y; acc.z += v.z; acc.w += v.w;
        ss += v.x * v.x + v.y * v.y + v.z * v.z + v.w * v.w;
    }

    // Dot folded q against the 12 kn rows of this head (L2-resident).
    const float4* kb = reinterpret_cast<const float4*>(g_kn + ((size_t)b * P + h * CK) * L);
    float dk[CK];
#pragma unroll
    for (int kk = 0; kk < CK; kk++) {
        float4 kv4 = kb[kk * 1024 + tid];
        dk[kk] = acc.x * kv4.x + acc.y * kv4.y + acc.z * kv4.z + acc.w * kv4.w;
    }

    // Block reduce: 12 dots + sum of squares.
    ss = warpSum(ss);
#pragma unroll
    for (int kk = 0; kk < CK; kk++) dk[kk] = warpSum(dk[kk]);

    __shared__ float sdk[32][CK];
    __shared__ float sss[32];
    __shared__ float logit[CK];
    __shared__ float snorm;
    if (lane == 0) {
        sss[w] = ss;
#pragma unroll
        for (int kk = 0; kk < CK; kk++) sdk[w][kk] = dk[kk];
    }
    __syncthreads();
    if (w < CK) {                       // warps 0..11: reduce one dot each
        float v = sdk[lane][w];
        v = warpSum(v);
        if (lane == 0) logit[w] = v;
    } else if (w == CK) {               // warp 12: reduce sum of squares
        float v = sss[lane];
        v = warpSum(v);
        if (lane == 0) snorm = fmaxf(sqrtf(v), 1e-12f);
    }
    __syncthreads();
    if (tid < CK) {
        float inv = 1.f / snorm;
        float mx = -1e30f;
#pragma unroll
        for (int k2 = 0; k2 < CK; k2++) mx = fmaxf(mx, logit[k2] * inv);
        float sum = 0.f;
#pragma unroll
        for (int k2 = 0; k2 < CK; k2++) sum += expf(logit[k2] * inv - mx);
        g_attn[(size_t)row * CK + tid] = expf(logit[tid] * inv - mx) / sum;
    }
}

// ---------------------------------------------------------------------------
// K4: M[b,o,h*12+kk] = sum_c W[o, h*48+c] * attn[b,h,c,kk]
// One block per (b,h) = 16 blocks x 384 threads (thread = o).
// attn slice in smem; 48 W coefficients in registers (MLP=48 on the loads).
// ---------------------------------------------------------------------------
__global__ void __launch_bounds__(384) k_fold_w(const float* __restrict__ W) {
    int bh = blockIdx.x;
    int b = bh >> 3, h = bh & 7;
    int o = threadIdx.x;

    __shared__ float sA[CQ * CK];       // attn[c][kk], 576 floats
    const float* ap = g_attn + ((size_t)b * CTOT + h * CQ) * CK;
    for (int i = o; i < CQ * CK; i += 384) sA[i] = ap[i];
    __syncthreads();

    float wreg[CQ];
    const float* wp = W + (size_t)o * CTOT + h * CQ;
#pragma unroll
    for (int cc = 0; cc < CQ; cc++) wreg[cc] = wp[cc];

    float* mp = g_M + ((size_t)b * CTOT + o) * P + h * CK;
#pragma unroll
    for (int kk = 0; kk < CK; kk++) {
        float s = 0.f;
#pragma unroll
        for (int cc = 0; cc < CQ; cc++) s += wreg[cc] * sA[cc * CK + kk];
        mp[kk] = s;
    }
}

// ---------------------------------------------------------------------------
// K5: f[b,o,j] = sum_p M[b,o,p] * kn[b,p,j]; write the value to all 16 tile
// replicas. Writes 201MB (dominant HBM write).
// Grid (jt=8, ot=48, b=2) = 768 blocks, 128 threads.
// Block tile: 8 o-rows x 512 j-cols (4 j per thread, float4).
// ---------------------------------------------------------------------------
__global__ void __launch_bounds__(128) k_out(float* __restrict__ out) {
    __shared__ float sM[8 * P];
    int jt = blockIdx.x, ot = blockIdx.y, b = blockIdx.z;
    int tid = threadIdx.x;

    const float* Mb = g_M + ((size_t)b * CTOT + ot * 8) * P;
    for (int i = tid; i < 8 * P; i += 128) sM[i] = Mb[i];
    __syncthreads();

    int j = jt * 512 + tid * 4;
    const float* knb = g_kn + (size_t)b * P * L + j;

    float4 acc[8];
#pragma unroll
    for (int oi = 0; oi < 8; oi++) acc[oi] = make_float4(0.f, 0.f, 0.f, 0.f);

#pragma unroll 4
    for (int pg = 0; pg < P; pg += 4) {
        float4 k0 = *reinterpret_cast<const float4*>(knb + (size_t)(pg + 0) * L);
        float4 k1 = *reinterpret_cast<const float4*>(knb + (size_t)(pg + 1) * L);
        float4 k2 = *reinterpret_cast<const float4*>(knb + (size_t)(pg + 2) * L);
        float4 k3 = *reinterpret_cast<const float4*>(knb + (size_t)(pg + 3) * L);
#pragma unroll
        for (int oi = 0; oi < 8; oi++) {
            float4 m = *reinterpret_cast<const float4*>(&sM[oi * P + pg]);
            acc[oi].x += m.x * k0.x + m.y * k1.x + m.z * k2.x + m.w * k3.x;
            acc[oi].y += m.x * k0.y + m.y * k1.y + m.z * k2.y + m.w * k3.y;
            acc[oi].z += m.x * k0.z + m.y * k1.z + m.z * k2.z + m.w * k3.z;
            acc[oi].w += m.x * k0.w + m.y * k1.w + m.z * k2.w + m.w * k3.w;
        }
    }

#pragma unroll
    for (int oi = 0; oi < 8; oi++) {
        size_t base = ((size_t)(b * CTOT + ot * 8 + oi)) * HW + j;
        float4 v = acc[oi];
#pragma unroll
        for (int t = 0; t < TREP; t++)
            *reinterpret_cast<float4*>(out + base + (size_t)t * L) = v;
    }
}

// ---------------------------------------------------------------------------
extern "C" void kernel_launch(void* const* d_in, const int* in_sizes, int n_in,
                              void* d_out, int out_size) {
    const float* Q  = (const float*)d_in[0];
    const float* kv = (const float*)d_in[1];
    const float* W  = (const float*)d_in[2];
    float* out = (float*)d_out;

    k_pool_kv<<<KROWS, 1024>>>(kv);
    k_fold_attn<<<NROWS, 1024>>>(Q);
    k_fold_w<<<B * HEADS, 384>>>(W);
    dim3 g5(8, 48, 2);
    k_out<<<g5, 128>>>(out);
}